// round 2
// baseline (speedup 1.0000x reference)
#include <cuda_runtime.h>
#include <math.h>

#define CCH   256
#define HW    384
#define NPIX  (HW*HW)        // 147456 elems per channel
#define NQ    (NPIX/4)       // 36864 float4 per channel
#define QPR   (HW/4)         // 96 float4 per row
#define INVN  (1.0f/(382.0f*382.0f))

// Scratch: window sums S[input][channel][9] and final per-channel coefficients.
__device__ float g_S[2][CCH][9];
__device__ float g_cf[2][CCH];

// ---------------------------------------------------------------------------
// Kernel 1: per-(input, channel) statistics -> 9 window sums.
// Window sum(kh,kw) over rows [kh,kh+382) x cols [kw,kw+382)
//   = Total - (excluded full-row sums) - (excluded full-col sums) + corners.
// Borders needed: rows/cols {0,1,382,383}; corners: 16 elems at their crossings.
// ---------------------------------------------------------------------------
__global__ void __launch_bounds__(512) stats_kernel(const float* __restrict__ in1,
                                                    const float* __restrict__ in2) {
    const int c     = blockIdx.x;
    const int which = blockIdx.y;
    const float4* x = (const float4*)((which ? in2 : in1) + (size_t)c * NPIX);
    const int tid   = threadIdx.x;

    float acc[9];   // tot, rs0,rs1,rs382,rs383, cs0,cs1,cs382,cs383
    #pragma unroll
    for (int j = 0; j < 9; j++) acc[j] = 0.0f;

    __shared__ float corn[16];      // [row-class 0..3][col-class 0..3]
    __shared__ float red[16][9];

    for (int i = tid; i < NQ; i += 512) {
        float4 v = x[i];
        int h = i / QPR;
        int q = i - h * QPR;
        float s = (v.x + v.y) + (v.z + v.w);
        acc[0] += s;
        if (h == 0)        acc[1] += s;
        else if (h == 1)   acc[2] += s;
        else if (h == 382) acc[3] += s;
        else if (h == 383) acc[4] += s;
        if (q == 0)       { acc[5] += v.x; acc[6] += v.y; }
        if (q == QPR - 1) { acc[7] += v.z; acc[8] += v.w; }
        bool hb = (h <= 1) | (h >= 382);
        if (hb) {
            int hi = (h <= 1) ? h : (h - 380);          // 0,1,2,3
            if (q == 0)       { corn[hi*4 + 0] = v.x; corn[hi*4 + 1] = v.y; }
            if (q == QPR - 1) { corn[hi*4 + 2] = v.z; corn[hi*4 + 3] = v.w; }
        }
    }

    // warp reduce then cross-warp reduce
    #pragma unroll
    for (int j = 0; j < 9; j++)
        #pragma unroll
        for (int off = 16; off > 0; off >>= 1)
            acc[j] += __shfl_down_sync(0xffffffffu, acc[j], off);
    int warp = tid >> 5, lane = tid & 31;
    if (lane == 0)
        #pragma unroll
        for (int j = 0; j < 9; j++) red[warp][j] = acc[j];
    __syncthreads();

    if (tid == 0) {
        float a[9];
        #pragma unroll
        for (int j = 0; j < 9; j++) {
            float s = 0.0f;
            #pragma unroll
            for (int w = 0; w < 16; w++) s += red[w][j];
            a[j] = s;
        }
        const float T = a[0];
        // excluded rows per kh: kh=0 -> {382,383}; kh=1 -> {0,383}; kh=2 -> {0,1}
        const int ER[3][2] = { {2,3}, {0,3}, {0,1} };
        float Rex[3] = { a[3]+a[4], a[1]+a[4], a[1]+a[2] };
        float Cex[3] = { a[7]+a[8], a[5]+a[8], a[5]+a[6] };
        #pragma unroll
        for (int kh = 0; kh < 3; kh++) {
            #pragma unroll
            for (int kw = 0; kw < 3; kw++) {
                float cor = 0.0f;
                #pragma unroll
                for (int i = 0; i < 2; i++)
                    #pragma unroll
                    for (int j = 0; j < 2; j++)
                        cor += corn[ER[kh][i]*4 + ER[kw][j]];
                g_S[which][c][kh*3 + kw] = T - Rex[kh] - Cex[kw] + cor;
            }
        }
    }
}

// ---------------------------------------------------------------------------
// Kernel 2: one block per output channel. m_i = b + (W[oc] . S_i)/N,
// S3 = S1+S2 by linearity. sigmoid (monotone, but matched to reference),
// branch flags -> per-channel combine coefficients.
// ---------------------------------------------------------------------------
__global__ void __launch_bounds__(256) coef_kernel(const float* __restrict__ W,
                                                   const float* __restrict__ b) {
    const int oc = blockIdx.x;
    const int ic = threadIdx.x;
    const float* wrow = W + (size_t)oc * CCH * 9 + ic * 9;
    float d1 = 0.0f, d2 = 0.0f;
    #pragma unroll
    for (int k = 0; k < 9; k++) {
        float w = wrow[k];
        d1 += w * g_S[0][ic][k];
        d2 += w * g_S[1][ic][k];
    }
    // block reduce (256 = 8 warps)
    #pragma unroll
    for (int off = 16; off > 0; off >>= 1) {
        d1 += __shfl_down_sync(0xffffffffu, d1, off);
        d2 += __shfl_down_sync(0xffffffffu, d2, off);
    }
    __shared__ float s1[8], s2[8];
    int warp = ic >> 5, lane = ic & 31;
    if (lane == 0) { s1[warp] = d1; s2[warp] = d2; }
    __syncthreads();
    if (ic == 0) {
        float D1 = 0.0f, D2 = 0.0f;
        #pragma unroll
        for (int w = 0; w < 8; w++) { D1 += s1[w]; D2 += s2[w]; }
        float bb = b[oc];
        float m1 = bb + D1 * INVN;
        float m2 = bb + D2 * INVN;
        float m3 = bb + (D1 + D2) * INVN;
        float x1 = 1.0f / (1.0f + expf(-m1));
        float x2 = 1.0f / (1.0f + expf(-m2));
        float x3 = 1.0f / (1.0f + expf(-m3));
        bool c1 = (x1 >= x2);
        bool c2 = (x1 <= x2);
        float a1 = (c1 && (x1 >= x3)) ? 1.0f : 0.0f;
        float a2 = (c2 && (x2 >= x3)) ? 1.0f : 0.0f;
        float a3 = ((c1 && (x1 < x3)) || (c2 && (x2 < x3))) ? 1.0f : 0.0f;
        g_cf[0][oc] = a1 + a3;   // multiplies input1
        g_cf[1][oc] = a2 + a3;   // multiplies input2
    }
}

// ---------------------------------------------------------------------------
// Kernel 3: out = k1[ch]*in1 + k2[ch]*in2, float4 vectorized.
// NQ (36864) is a multiple of 256, so every block lies in a single channel.
// ---------------------------------------------------------------------------
__global__ void __launch_bounds__(256) combine_kernel(const float4* __restrict__ in1,
                                                      const float4* __restrict__ in2,
                                                      float4* __restrict__ out) {
    const int ch  = blockIdx.x / (NQ / 256);          // 144 blocks per channel
    const int idx = blockIdx.x * 256 + threadIdx.x;
    const float k1 = g_cf[0][ch];
    const float k2 = g_cf[1][ch];
    float4 a = in1[idx];
    float4 b = in2[idx];
    float4 o;
    o.x = k1 * a.x + k2 * b.x;
    o.y = k1 * a.y + k2 * b.y;
    o.z = k1 * a.z + k2 * b.z;
    o.w = k1 * a.w + k2 * b.w;
    out[idx] = o;
}

extern "C" void kernel_launch(void* const* d_in, const int* in_sizes, int n_in,
                              void* d_out, int out_size) {
    const float* in1 = (const float*)d_in[0];
    const float* in2 = (const float*)d_in[1];
    const float* W   = (const float*)d_in[2];
    const float* b   = (const float*)d_in[3];
    float* out = (float*)d_out;

    stats_kernel<<<dim3(CCH, 2), 512>>>(in1, in2);
    coef_kernel<<<CCH, 256>>>(W, b);
    combine_kernel<<<CCH * (NQ / 256), 256>>>((const float4*)in1,
                                              (const float4*)in2,
                                              (float4*)out);
}

// round 3
// speedup vs baseline: 1.0158x; 1.0158x over previous
#include <cuda_runtime.h>
#include <math.h>

#define CCH   256
#define HW    384
#define NPIX  (HW*HW)        // 147456 elems per channel
#define NQ    (NPIX/4)       // 36864 float4 per channel
#define QPR   (HW/4)         // 96 float4 per row
#define INVN  (1.0f/(382.0f*382.0f))

// Scratch: window sums S[input][channel][9] and final per-channel coefficients.
__device__ float g_S[2][CCH][9];
__device__ float g_cf[2][CCH];

// ---------------------------------------------------------------------------
// Kernel 1: per-(input, channel) statistics -> 9 window sums.
// 384 threads: r0 = tid/96 in [0,4), q = tid%96. Iteration j handles row 4j+r0.
// Rows {0,1} live only in j=0 (r0<2), rows {382,383} only in j=95 (r0>=2):
// peel those, leaving a branch-free streaming interior loop. Column-boundary
// predicates (q==0 / q==95) are loop-invariant per thread.
// ---------------------------------------------------------------------------
__global__ void __launch_bounds__(384) stats_kernel(const float* __restrict__ in1,
                                                    const float* __restrict__ in2) {
    const int c     = blockIdx.x;
    const int which = blockIdx.y;
    const float4* x = ((const float4*)(which ? in2 : in1)) + (size_t)c * NQ;

    const int tid = threadIdx.x;
    const int r0  = tid / 96;          // 0..3
    const int q   = tid - r0 * 96;     // 0..95
    const bool q0  = (q == 0);
    const bool q95 = (q == 95);

    __shared__ float corn[16];         // [row-class][col-class]
    __shared__ float rowsh[4];         // row sums for rows 0,1,382,383
    __shared__ float colsh[4];         // col sums for cols 0,1,382,383
    __shared__ float red[12];          // per-warp totals
    if (tid < 4) { rowsh[tid] = 0.0f; colsh[tid] = 0.0f; }

    const float4* p = x + (size_t)(r0 * 96 + q);   // row r0, advance 384/iter

    float tot = 0.0f;
    float c0 = 0.0f, c1 = 0.0f, c2 = 0.0f, c3 = 0.0f;  // col-boundary accs
    float accR = 0.0f;                                  // my border-row sum

    // ---- peeled j = 0 (rows 0..3) ----
    {
        float4 v = __ldcs(p);
        float s = (v.x + v.y) + (v.z + v.w);
        tot += s;
        if (q0)  { c0 += v.x; c1 += v.y; }
        if (q95) { c2 += v.z; c3 += v.w; }
        if (r0 < 2) {
            accR += s;
            if (q0)  { corn[r0*4 + 0] = v.x; corn[r0*4 + 1] = v.y; }
            if (q95) { corn[r0*4 + 2] = v.z; corn[r0*4 + 3] = v.w; }
        }
        p += 384;
    }

    // ---- interior j = 1..94: branch-light streaming ----
    #pragma unroll 4
    for (int j = 1; j < 95; j++) {
        float4 v = __ldcs(p);
        p += 384;
        tot += (v.x + v.y) + (v.z + v.w);
        if (q0)  { c0 += v.x; c1 += v.y; }
        if (q95) { c2 += v.z; c3 += v.w; }
    }

    // ---- peeled j = 95 (rows 380..383) ----
    {
        float4 v = __ldcs(p);
        float s = (v.x + v.y) + (v.z + v.w);
        tot += s;
        if (q0)  { c0 += v.x; c1 += v.y; }
        if (q95) { c2 += v.z; c3 += v.w; }
        if (r0 >= 2) {                  // rows 382 (r0=2), 383 (r0=3)
            accR += s;
            if (q0)  { corn[r0*4 + 0] = v.x; corn[r0*4 + 1] = v.y; }
            if (q95) { corn[r0*4 + 2] = v.z; corn[r0*4 + 3] = v.w; }
        }
    }

    __syncthreads();   // init of rowsh/colsh + corn writes ordered

    // border-row partial sums (96 threads per class) and col sums (4 threads each)
    atomicAdd(&rowsh[r0], accR);
    if (q0)  { atomicAdd(&colsh[0], c0); atomicAdd(&colsh[1], c1); }
    if (q95) { atomicAdd(&colsh[2], c2); atomicAdd(&colsh[3], c3); }

    // total: warp shuffle + cross-warp
    #pragma unroll
    for (int off = 16; off > 0; off >>= 1)
        tot += __shfl_down_sync(0xffffffffu, tot, off);
    int warp = tid >> 5, lane = tid & 31;
    if (lane == 0) red[warp] = tot;
    __syncthreads();

    if (tid == 0) {
        float T = 0.0f;
        #pragma unroll
        for (int w = 0; w < 12; w++) T += red[w];
        // excluded border classes per kernel offset: kh=0 -> {2,3}; kh=1 -> {0,3}; kh=2 -> {0,1}
        const int ER[3][2] = { {2,3}, {0,3}, {0,1} };
        float Rex[3] = { rowsh[2]+rowsh[3], rowsh[0]+rowsh[3], rowsh[0]+rowsh[1] };
        float Cex[3] = { colsh[2]+colsh[3], colsh[0]+colsh[3], colsh[0]+colsh[1] };
        #pragma unroll
        for (int kh = 0; kh < 3; kh++) {
            #pragma unroll
            for (int kw = 0; kw < 3; kw++) {
                float cor = 0.0f;
                #pragma unroll
                for (int i = 0; i < 2; i++)
                    #pragma unroll
                    for (int j = 0; j < 2; j++)
                        cor += corn[ER[kh][i]*4 + ER[kw][j]];
                g_S[which][c][kh*3 + kw] = T - Rex[kh] - Cex[kw] + cor;
            }
        }
    }
}

// ---------------------------------------------------------------------------
// Kernel 2: per-output-channel matvec + sigmoid + branch flags -> coefficients.
// ---------------------------------------------------------------------------
__global__ void __launch_bounds__(256) coef_kernel(const float* __restrict__ W,
                                                   const float* __restrict__ b) {
    const int oc = blockIdx.x;
    const int ic = threadIdx.x;
    const float* wrow = W + (size_t)oc * CCH * 9 + ic * 9;
    float d1 = 0.0f, d2 = 0.0f;
    #pragma unroll
    for (int k = 0; k < 9; k++) {
        float w = wrow[k];
        d1 += w * g_S[0][ic][k];
        d2 += w * g_S[1][ic][k];
    }
    #pragma unroll
    for (int off = 16; off > 0; off >>= 1) {
        d1 += __shfl_down_sync(0xffffffffu, d1, off);
        d2 += __shfl_down_sync(0xffffffffu, d2, off);
    }
    __shared__ float s1[8], s2[8];
    int warp = ic >> 5, lane = ic & 31;
    if (lane == 0) { s1[warp] = d1; s2[warp] = d2; }
    __syncthreads();
    if (ic == 0) {
        float D1 = 0.0f, D2 = 0.0f;
        #pragma unroll
        for (int w = 0; w < 8; w++) { D1 += s1[w]; D2 += s2[w]; }
        float bb = b[oc];
        float m1 = bb + D1 * INVN;
        float m2 = bb + D2 * INVN;
        float m3 = bb + (D1 + D2) * INVN;
        float x1 = 1.0f / (1.0f + expf(-m1));
        float x2 = 1.0f / (1.0f + expf(-m2));
        float x3 = 1.0f / (1.0f + expf(-m3));
        bool c1 = (x1 >= x2);
        bool c2 = (x1 <= x2);
        float a1 = (c1 && (x1 >= x3)) ? 1.0f : 0.0f;
        float a2 = (c2 && (x2 >= x3)) ? 1.0f : 0.0f;
        float a3 = ((c1 && (x1 < x3)) || (c2 && (x2 < x3))) ? 1.0f : 0.0f;
        g_cf[0][oc] = a1 + a3;   // multiplies input1
        g_cf[1][oc] = a2 + a3;   // multiplies input2
    }
}

// ---------------------------------------------------------------------------
// Kernel 3: out = k1[ch]*in1 + k2[ch]*in2, float4 streaming.
// ---------------------------------------------------------------------------
__global__ void __launch_bounds__(256) combine_kernel(const float4* __restrict__ in1,
                                                      const float4* __restrict__ in2,
                                                      float4* __restrict__ out) {
    const int ch  = blockIdx.x / (NQ / 256);          // 144 blocks per channel
    const int idx = blockIdx.x * 256 + threadIdx.x;
    const float k1 = g_cf[0][ch];
    const float k2 = g_cf[1][ch];
    float4 a = __ldcs(in1 + idx);
    float4 b = __ldcs(in2 + idx);
    float4 o;
    o.x = k1 * a.x + k2 * b.x;
    o.y = k1 * a.y + k2 * b.y;
    o.z = k1 * a.z + k2 * b.z;
    o.w = k1 * a.w + k2 * b.w;
    __stcs(out + idx, o);
}

extern "C" void kernel_launch(void* const* d_in, const int* in_sizes, int n_in,
                              void* d_out, int out_size) {
    const float* in1 = (const float*)d_in[0];
    const float* in2 = (const float*)d_in[1];
    const float* W   = (const float*)d_in[2];
    const float* b   = (const float*)d_in[3];
    float* out = (float*)d_out;

    stats_kernel<<<dim3(CCH, 2), 384>>>(in1, in2);
    coef_kernel<<<CCH, 256>>>(W, b);
    combine_kernel<<<CCH * (NQ / 256), 256>>>((const float4*)in1,
                                              (const float4*)in2,
                                              (float4*)out);
}